// round 10
// baseline (speedup 1.0000x reference)
#include <cuda_runtime.h>
#include <math_constants.h>

// Problem constants
#define BATCH 4
#define SEQ   2048
#define DIM   512
#define NH    8
#define HD    64
#define QKV_E (3 * DIM)      // 1536
#define ROWS  (BATCH * SEQ)  // 8192

// ---------------------------------------------------------------------------
// Scratch (allocation-free rule: __device__ globals). Word = unsigned (bf16x2).
// ---------------------------------------------------------------------------
__device__ float    g_q  [(size_t)ROWS * DIM];        // Q fp32, row-major [b*s, 512]
__device__ unsigned g_kh [(size_t)ROWS * DIM / 2];    // K bf16 hi, head-major [b,h,s,32w]
__device__ unsigned g_kl [(size_t)ROWS * DIM / 2];    // K bf16 lo
__device__ float    g_vr [(size_t)ROWS * DIM];        // V fp32 (tf32-rounded), head-major
__device__ unsigned g_oh [(size_t)ROWS * DIM / 2];    // attn out bf16 hi, row-major words
__device__ unsigned g_ol [(size_t)ROWS * DIM / 2];    // attn out bf16 lo
__device__ unsigned g_xh [(size_t)ROWS * DIM / 2];    // x bf16 hi
__device__ unsigned g_xl [(size_t)ROWS * DIM / 2];    // x bf16 lo
__device__ unsigned g_wqh[(size_t)QKV_E * DIM / 2];   // w_qkv bf16 hi
__device__ unsigned g_wql[(size_t)QKV_E * DIM / 2];
__device__ unsigned g_woh[(size_t)DIM * DIM / 2];     // w_out bf16 hi
__device__ unsigned g_wol[(size_t)DIM * DIM / 2];

// ---------------------------------------------------------------------------
// helpers
// ---------------------------------------------------------------------------
__device__ __forceinline__ unsigned f2tf(float f) {   // round-to-nearest tf32 bits
    unsigned r;
    asm("cvt.rna.tf32.f32 %0, %1;" : "=r"(r) : "f"(f));
    return r;
}
__device__ __forceinline__ unsigned bfpack(float f_even, float f_odd) {
    unsigned r;
    asm("cvt.rn.bf16x2.f32 %0, %1, %2;" : "=r"(r) : "f"(f_odd), "f"(f_even));
    return r;
}
__device__ __forceinline__ unsigned bflo(float f_even, float f_odd, unsigned h) {
    float r0 = f_even - __uint_as_float(h << 16);
    float r1 = f_odd  - __uint_as_float(h & 0xffff0000u);
    return bfpack(r0, r1);
}
__device__ __forceinline__ void mma_bf16(float c[4], const unsigned a[4],
                                         unsigned b0, unsigned b1) {
    asm volatile(
        "mma.sync.aligned.m16n8k16.row.col.f32.bf16.bf16.f32 "
        "{%0,%1,%2,%3}, {%4,%5,%6,%7}, {%8,%9}, {%0,%1,%2,%3};"
        : "+f"(c[0]), "+f"(c[1]), "+f"(c[2]), "+f"(c[3])
        : "r"(a[0]), "r"(a[1]), "r"(a[2]), "r"(a[3]), "r"(b0), "r"(b1));
}
__device__ __forceinline__ void mma_tf32(float c[4], const unsigned a[4],
                                         unsigned b0, unsigned b1) {
    asm volatile(
        "mma.sync.aligned.m16n8k8.row.col.f32.tf32.tf32.f32 "
        "{%0,%1,%2,%3}, {%4,%5,%6,%7}, {%8,%9}, {%0,%1,%2,%3};"
        : "+f"(c[0]), "+f"(c[1]), "+f"(c[2]), "+f"(c[3])
        : "r"(a[0]), "r"(a[1]), "r"(a[2]), "r"(a[3]), "r"(b0), "r"(b1));
}
__device__ __forceinline__ void cp16(unsigned sdst, const void* gsrc) {
    asm volatile("cp.async.cg.shared.global [%0], [%1], 16;"
                 :: "r"(sdst), "l"(gsrc) : "memory");
}
__device__ __forceinline__ void cp_commit() {
    asm volatile("cp.async.commit_group;" ::: "memory");
}
__device__ __forceinline__ void cp_wait1() {
    asm volatile("cp.async.wait_group 1;" ::: "memory");
}

// ---------------------------------------------------------------------------
// convert pass: fp32 -> bf16 hi/lo word arrays
// ---------------------------------------------------------------------------
__global__ void cvt_bf(const float* __restrict__ s, unsigned* __restrict__ h,
                       unsigned* __restrict__ l, int npairs)
{
    for (int i = blockIdx.x * blockDim.x + threadIdx.x; i < npairs;
         i += gridDim.x * blockDim.x) {
        float2 v = reinterpret_cast<const float2*>(s)[i];
        unsigned hi = bfpack(v.x, v.y);
        h[i] = hi;
        l[i] = bflo(v.x, v.y, hi);
    }
}

// ---------------------------------------------------------------------------
// bf16x3 GEMM from pre-split bf16 operands, cp.async double-buffered.
// C[M,N] = A[M,K] * W[N,K]^T. CTA 128x128, 256 threads = 8 warps (4 m-rows x
// 2 n-cols of warps); each warp: 32 rows (2 m16) x 64 cols (8 n8). k-step 32.
// mode 0: plain fp32 C. mode 1: QKV split epilogue (q fp32 / k bf16hl / v rnd).
// ---------------------------------------------------------------------------
#define GLA 20                 // words per 32-bf16 row (16 data + 4 pad)
#define GSTG 10240             // words per stage: (128+128+128+128)*20
#define GEMM_SMEM (2 * GSTG * 4)   // 81920 B

__global__ __launch_bounds__(256, 2) void gemm_bf16p(
    const unsigned* __restrict__ Ah, const unsigned* __restrict__ Al,
    const unsigned* __restrict__ Wh, const unsigned* __restrict__ Wl,
    float* __restrict__ C, int M, int N, int K, int mode,
    float* __restrict__ qout, unsigned* __restrict__ khw,
    unsigned* __restrict__ klw, float* __restrict__ vrw)
{
    extern __shared__ __align__(16) unsigned smem_u[];
    const unsigned sb = (unsigned)__cvta_generic_to_shared(smem_u);

    const int tid  = threadIdx.x;
    const int warp = tid >> 5;
    const int wm   = warp >> 1;        // 0..3 (m direction)
    const int wn   = warp & 1;         // 0..1 (n direction)
    const int lane = tid & 31;
    const int g    = lane >> 2;
    const int c    = lane & 3;
    const int m0   = blockIdx.y * 128;
    const int n0   = blockIdx.x * 128;
    const int Kw   = K >> 1;

    auto issue = [&](int k0, int buf) {
        unsigned base = sb + buf * GSTG * 4;
        int k0w = k0 >> 1;
#pragma unroll
        for (int it = 0; it < 8; it++) {
            int cid = it * 256 + tid;       // 0..2047
            int row = (cid >> 2) & 127;
            int ch  = cid & 3;
            if (cid < 512) {
                cp16(base + (row * GLA + ch * 4) * 4,
                     Ah + (size_t)(m0 + row) * Kw + k0w + ch * 4);
            } else if (cid < 1024) {
                cp16(base + (2560 + row * GLA + ch * 4) * 4,
                     Al + (size_t)(m0 + row) * Kw + k0w + ch * 4);
            } else if (cid < 1536) {
                cp16(base + (5120 + row * GLA + ch * 4) * 4,
                     Wh + (size_t)(n0 + row) * Kw + k0w + ch * 4);
            } else {
                cp16(base + (7680 + row * GLA + ch * 4) * 4,
                     Wl + (size_t)(n0 + row) * Kw + k0w + ch * 4);
            }
        }
    };

    float acc[2][8][4];
#pragma unroll
    for (int mt = 0; mt < 2; mt++)
#pragma unroll
        for (int nt = 0; nt < 8; nt++)
#pragma unroll
            for (int i = 0; i < 4; i++) acc[mt][nt][i] = 0.0f;

    const int NT = K / 32;    // 16
    issue(0, 0);  cp_commit();
    issue(32, 1); cp_commit();

    for (int kt = 0; kt < NT; kt++) {
        cp_wait1();
        __syncthreads();
        const unsigned* bAh = smem_u + (kt & 1) * GSTG;
        const unsigned* bAl = bAh + 2560;
        const unsigned* bWh = bAh + 5120;
        const unsigned* bWl = bAh + 7680;

#pragma unroll
        for (int ks = 0; ks < 2; ks++) {
            unsigned ah[2][4], al[2][4];
#pragma unroll
            for (int mt = 0; mt < 2; mt++) {
                int rA = wm * 32 + mt * 16 + g;
                ah[mt][0] = bAh[rA * GLA + ks * 8 + c];
                ah[mt][1] = bAh[(rA + 8) * GLA + ks * 8 + c];
                ah[mt][2] = bAh[rA * GLA + ks * 8 + c + 4];
                ah[mt][3] = bAh[(rA + 8) * GLA + ks * 8 + c + 4];
                al[mt][0] = bAl[rA * GLA + ks * 8 + c];
                al[mt][1] = bAl[(rA + 8) * GLA + ks * 8 + c];
                al[mt][2] = bAl[rA * GLA + ks * 8 + c + 4];
                al[mt][3] = bAl[(rA + 8) * GLA + ks * 8 + c + 4];
            }
#pragma unroll
            for (int nt = 0; nt < 8; nt++) {
                int rB = wn * 64 + nt * 8 + g;
                unsigned bh0 = bWh[rB * GLA + ks * 8 + c];
                unsigned bh1 = bWh[rB * GLA + ks * 8 + c + 4];
                unsigned bl0 = bWl[rB * GLA + ks * 8 + c];
                unsigned bl1 = bWl[rB * GLA + ks * 8 + c + 4];
                // pass-major ordering: dependent-MMA gap of 2
                mma_bf16(acc[0][nt], ah[0], bh0, bh1);
                mma_bf16(acc[1][nt], ah[1], bh0, bh1);
                mma_bf16(acc[0][nt], ah[0], bl0, bl1);
                mma_bf16(acc[1][nt], ah[1], bl0, bl1);
                mma_bf16(acc[0][nt], al[0], bh0, bh1);
                mma_bf16(acc[1][nt], al[1], bh0, bh1);
            }
        }
        __syncthreads();
        if (kt + 2 < NT) issue((kt + 2) * 32, kt & 1);
        cp_commit();
    }

    // ---- epilogue (warp column base nb selects q/k/v region in mode 1) ----
    const int nb = n0 + wn * 64;
    if (mode == 0) {
#pragma unroll
        for (int mt = 0; mt < 2; mt++) {
            int r0 = m0 + wm * 32 + mt * 16 + g;
#pragma unroll
            for (int nt = 0; nt < 8; nt++) {
                *reinterpret_cast<float2*>(C + (size_t)r0 * N + nb + nt * 8 + 2 * c) =
                    make_float2(acc[mt][nt][0], acc[mt][nt][1]);
                *reinterpret_cast<float2*>(C + (size_t)(r0 + 8) * N + nb + nt * 8 + 2 * c) =
                    make_float2(acc[mt][nt][2], acc[mt][nt][3]);
            }
        }
    } else if (nb < DIM) {
        // q region: plain fp32 into g_q
#pragma unroll
        for (int mt = 0; mt < 2; mt++) {
            int r0 = m0 + wm * 32 + mt * 16 + g;
#pragma unroll
            for (int nt = 0; nt < 8; nt++) {
                *reinterpret_cast<float2*>(qout + (size_t)r0 * DIM + nb + nt * 8 + 2 * c) =
                    make_float2(acc[mt][nt][0], acc[mt][nt][1]);
                *reinterpret_cast<float2*>(qout + (size_t)(r0 + 8) * DIM + nb + nt * 8 + 2 * c) =
                    make_float2(acc[mt][nt][2], acc[mt][nt][3]);
            }
        }
    } else if (nb < 2 * DIM) {
        // k region: bf16 hi/lo, head-major [b, h, s, 32 words]
        int hh = (nb - DIM) >> 6;
        size_t rowb = ((size_t)((m0 >> 11) * NH + hh)) * SEQ + (m0 & 2047);
#pragma unroll
        for (int mt = 0; mt < 2; mt++) {
            int lr = wm * 32 + mt * 16 + g;
#pragma unroll
            for (int nt = 0; nt < 8; nt++) {
                unsigned h0 = bfpack(acc[mt][nt][0], acc[mt][nt][1]);
                size_t i0 = (rowb + lr) * 32 + nt * 4 + c;
                khw[i0] = h0;
                klw[i0] = bflo(acc[mt][nt][0], acc[mt][nt][1], h0);
                unsigned h1 = bfpack(acc[mt][nt][2], acc[mt][nt][3]);
                size_t i1 = (rowb + lr + 8) * 32 + nt * 4 + c;
                khw[i1] = h1;
                klw[i1] = bflo(acc[mt][nt][2], acc[mt][nt][3], h1);
            }
        }
    } else {
        // v region: tf32-rounded fp32, head-major [b, h, s, 64]
        int hh = (nb - 2 * DIM) >> 6;
        size_t rowb = ((size_t)((m0 >> 11) * NH + hh)) * SEQ + (m0 & 2047);
#pragma unroll
        for (int mt = 0; mt < 2; mt++) {
            int lr = wm * 32 + mt * 16 + g;
#pragma unroll
            for (int nt = 0; nt < 8; nt++) {
                *reinterpret_cast<float2*>(vrw + (rowb + lr) * HD + nt * 8 + 2 * c) =
                    make_float2(__uint_as_float(f2tf(acc[mt][nt][0])),
                                __uint_as_float(f2tf(acc[mt][nt][1])));
                *reinterpret_cast<float2*>(vrw + (rowb + lr + 8) * HD + nt * 8 + 2 * c) =
                    make_float2(__uint_as_float(f2tf(acc[mt][nt][2])),
                                __uint_as_float(f2tf(acc[mt][nt][3])));
            }
        }
    }
}

// ---------------------------------------------------------------------------
// Fused attention: per key-tile, for each 8-key block nt: S = QK^T (bf16x3),
// P = round_tf32(exp(S-24)) kept in REGISTERS (quad shuffles convert the
// accumulator layout to the tf32 A-fragment layout), then immediately
// O += P V (tf32). No P SMEM round-trip -> smem 73.7KB -> 3 CTAs/SM.
// 128 queries/CTA, 4 warps x 2 m16-tiles, key tiles of 64, cp.async ring.
// ---------------------------------------------------------------------------
#define LDP 68                  // Q staging stride (floats), stage0 reuse
#define LDKW 36                 // K stage row stride (words: 32 data + 4 pad)
#define LDV 72                  // V stage row stride (words)
#define ATT_STG (64 * LDKW * 2 + 64 * LDV)   // 9216 words per stage
#define ATT_SMEM (2 * ATT_STG * 4)           // 73728 B

__global__ __launch_bounds__(128, 3) void attn_tc(
    const float* __restrict__ qg, const unsigned* __restrict__ khw,
    const unsigned* __restrict__ klw, const float* __restrict__ vr,
    unsigned* __restrict__ ohw, unsigned* __restrict__ olw)
{
    extern __shared__ __align__(16) unsigned smem_u[];
    const unsigned sb = (unsigned)__cvta_generic_to_shared(smem_u);
    float* sPf = reinterpret_cast<float*>(smem_u);   // Q staging (stage0 space)

    const int tid  = threadIdx.x;
    const int warp = tid >> 5;
    const int lane = tid & 31;
    const int g    = lane >> 2;
    const int c    = lane & 3;

    const int h  = blockIdx.y;
    const int b  = blockIdx.z;
    const int q0 = blockIdx.x * 128;
    const int bh8 = b * NH + h;

    auto issue = [&](int kt, int stage) {
        unsigned base = sb + stage * ATT_STG * 4;
        size_t tb = (size_t)bh8 * SEQ + kt * 64;   // head-major row base
#pragma unroll
        for (int it = 0; it < 16; it++) {
            int cid = it * 128 + tid;
            if (cid < 512) {
                int row = cid >> 3, ch = cid & 7;
                cp16(base + (row * LDKW + ch * 4) * 4, khw + (tb + row) * 32 + ch * 4);
            } else if (cid < 1024) {
                int c2 = cid - 512; int row = c2 >> 3, ch = c2 & 7;
                cp16(base + (64 * LDKW + row * LDKW + ch * 4) * 4,
                     klw + (tb + row) * 32 + ch * 4);
            } else {
                int c2 = cid - 1024; int row = c2 >> 4, ch = c2 & 15;
                cp16(base + (128 * LDKW + row * LDV + ch * 4) * 4,
                     vr + (tb + row) * HD + ch * 4);
            }
        }
    };

    // ---- stage Q tile (128x64 fp32) into stage0 space, build bf16 frags ----
    const float* qbase = qg + (size_t)b * SEQ * DIM + h * HD;
#pragma unroll
    for (int it = 0; it < 16; it++) {
        int idx = it * 128 + tid;
        int row = idx >> 4;
        int seg = (idx & 15) * 4;
        *reinterpret_cast<float4*>(&sPf[row * LDP + seg]) =
            *reinterpret_cast<const float4*>(qbase + (size_t)(q0 + row) * DIM + seg);
    }
    __syncthreads();

    unsigned qh[2][4][4], ql[2][4][4];
#pragma unroll
    for (int mt = 0; mt < 2; mt++) {
        int r0 = warp * 32 + mt * 16 + g;
#pragma unroll
        for (int ks = 0; ks < 4; ks++) {
            float2 e00 = *reinterpret_cast<float2*>(&sPf[r0 * LDP + ks * 16 + 2 * c]);
            float2 e10 = *reinterpret_cast<float2*>(&sPf[(r0 + 8) * LDP + ks * 16 + 2 * c]);
            float2 e01 = *reinterpret_cast<float2*>(&sPf[r0 * LDP + ks * 16 + 2 * c + 8]);
            float2 e11 = *reinterpret_cast<float2*>(&sPf[(r0 + 8) * LDP + ks * 16 + 2 * c + 8]);
            qh[mt][ks][0] = bfpack(e00.x, e00.y);
            qh[mt][ks][1] = bfpack(e10.x, e10.y);
            qh[mt][ks][2] = bfpack(e01.x, e01.y);
            qh[mt][ks][3] = bfpack(e11.x, e11.y);
            ql[mt][ks][0] = bflo(e00.x, e00.y, qh[mt][ks][0]);
            ql[mt][ks][1] = bflo(e10.x, e10.y, qh[mt][ks][1]);
            ql[mt][ks][2] = bflo(e01.x, e01.y, qh[mt][ks][2]);
            ql[mt][ks][3] = bflo(e11.x, e11.y, qh[mt][ks][3]);
        }
    }
    __syncthreads();   // staging area free before cp.async overwrites it

    issue(0, 0); cp_commit();
    issue(1, 1); cp_commit();

    float O[2][8][4];
#pragma unroll
    for (int mt = 0; mt < 2; mt++)
#pragma unroll
        for (int nt = 0; nt < 8; nt++)
#pragma unroll
            for (int i = 0; i < 4; i++) O[mt][nt][i] = 0.0f;
    float lsum[2][2] = {{0.0f, 0.0f}, {0.0f, 0.0f}};

    const int srcA = (lane & ~3) + (c >> 1);   // quad-shuffle sources
    const int srcB = srcA + 2;
    const bool odd = (c & 1);

    for (int kt = 0; kt < SEQ / 64; kt++) {
        cp_wait1();
        __syncthreads();
        const unsigned* bKh = smem_u + (kt & 1) * ATT_STG;
        const unsigned* bKl = bKh + 64 * LDKW;
        const unsigned* bV  = bKh + 128 * LDKW;

#pragma unroll
        for (int nt = 0; nt < 8; nt++) {
            // ---- S = Q K^T (bf16x3) for 8-key block nt ----
            float s4[2][4];
#pragma unroll
            for (int mt = 0; mt < 2; mt++)
#pragma unroll
                for (int i = 0; i < 4; i++) s4[mt][i] = 0.0f;
            int rB = nt * 8 + g;
#pragma unroll
            for (int ks = 0; ks < 4; ks++) {
                unsigned bh0 = bKh[rB * LDKW + ks * 8 + c];
                unsigned bh1 = bKh[rB * LDKW + ks * 8 + c + 4];
                unsigned bl0 = bKl[rB * LDKW + ks * 8 + c];
                unsigned bl1 = bKl[rB * LDKW + ks * 8 + c + 4];
                mma_bf16(s4[0], qh[0][ks], bh0, bh1);
                mma_bf16(s4[1], qh[1][ks], bh0, bh1);
                mma_bf16(s4[0], qh[0][ks], bl0, bl1);
                mma_bf16(s4[1], qh[1][ks], bl0, bl1);
                mma_bf16(s4[0], ql[0][ks], bh0, bh1);
                mma_bf16(s4[1], ql[1][ks], bh0, bh1);
            }

            // ---- P = round_tf32(exp(S-24)); accum layout -> A-frag layout
            //      via quad shuffles (cols 2c,2c+1 -> cols c, c+4) ----
            unsigned pa[2][4];
#pragma unroll
            for (int mt = 0; mt < 2; mt++) {
                float p0 = __uint_as_float(f2tf(__expf(s4[mt][0] - 24.0f)));
                float p1 = __uint_as_float(f2tf(__expf(s4[mt][1] - 24.0f)));
                float p2 = __uint_as_float(f2tf(__expf(s4[mt][2] - 24.0f)));
                float p3 = __uint_as_float(f2tf(__expf(s4[mt][3] - 24.0f)));
                lsum[mt][0] += p0 + p1;
                lsum[mt][1] += p2 + p3;
                float v0 = __shfl_sync(0xffffffffu, p0, srcA);
                float v1 = __shfl_sync(0xffffffffu, p1, srcA);
                float u0 = __shfl_sync(0xffffffffu, p0, srcB);
                float u1 = __shfl_sync(0xffffffffu, p1, srcB);
                float w0 = __shfl_sync(0xffffffffu, p2, srcA);
                float w1 = __shfl_sync(0xffffffffu, p3, srcA);
                float x0 = __shfl_sync(0xffffffffu, p2, srcB);
                float x1 = __shfl_sync(0xffffffffu, p3, srcB);
                pa[mt][0] = __float_as_uint(odd ? v1 : v0);  // row g,   col c
                pa[mt][1] = __float_as_uint(odd ? w1 : w0);  // row g+8, col c
                pa[mt][2] = __float_as_uint(odd ? u1 : u0);  // row g,   col c+4
                pa[mt][3] = __float_as_uint(odd ? x1 : x0);  // row g+8, col c+4
            }

            // ---- O += P V (tf32) for key block kk == nt ----
#pragma unroll
            for (int ntv = 0; ntv < 8; ntv++) {
                unsigned vh0 = bV[(nt * 8 + c) * LDV + ntv * 8 + g];
                unsigned vh1 = bV[(nt * 8 + c + 4) * LDV + ntv * 8 + g];
                mma_tf32(O[0][ntv], pa[0], vh0, vh1);
                mma_tf32(O[1][ntv], pa[1], vh0, vh1);
            }
        }

        __syncthreads();    // all warps done with this stage's K/V
        if (kt + 2 < SEQ / 64) issue(kt + 2, kt & 1);
        cp_commit();
    }

    // ---- normalize and store as bf16 hi/lo (out-proj A operand) ----
#pragma unroll
    for (int mt = 0; mt < 2; mt++)
#pragma unroll
        for (int i = 0; i < 2; i++) {
            lsum[mt][i] += __shfl_xor_sync(0xffffffffu, lsum[mt][i], 1);
            lsum[mt][i] += __shfl_xor_sync(0xffffffffu, lsum[mt][i], 2);
        }

#pragma unroll
    for (int mt = 0; mt < 2; mt++) {
        const float inv0 = 1.0f / lsum[mt][0];
        const float inv1 = 1.0f / lsum[mt][1];
        int qr = q0 + warp * 32 + mt * 16 + g;
        size_t r0w = ((size_t)b * SEQ + qr) * (DIM / 2) + h * (HD / 2);
        size_t r1w = ((size_t)b * SEQ + qr + 8) * (DIM / 2) + h * (HD / 2);
#pragma unroll
        for (int nt = 0; nt < 8; nt++) {
            float o0 = O[mt][nt][0] * inv0, o1 = O[mt][nt][1] * inv0;
            float o2 = O[mt][nt][2] * inv1, o3 = O[mt][nt][3] * inv1;
            unsigned h0 = bfpack(o0, o1);
            ohw[r0w + nt * 4 + c] = h0;
            olw[r0w + nt * 4 + c] = bflo(o0, o1, h0);
            unsigned h1 = bfpack(o2, o3);
            ohw[r1w + nt * 4 + c] = h1;
            olw[r1w + nt * 4 + c] = bflo(o2, o3, h1);
        }
    }
}

// ---------------------------------------------------------------------------
extern "C" void kernel_launch(void* const* d_in, const int* in_sizes, int n_in,
                              void* d_out, int out_size)
{
    const float* x     = (const float*)d_in[0];  // [4, 2048, 512]
    const float* w_qkv = (const float*)d_in[1];  // [1536, 512]
    const float* w_out = (const float*)d_in[2];  // [512, 512]
    float* out = (float*)d_out;                  // [4, 2048, 512]

    float *qb, *vb;
    unsigned *khb, *klb, *ohb, *olb, *xhb, *xlb, *wqh, *wql, *woh, *wol;
    cudaGetSymbolAddress((void**)&qb,  g_q);
    cudaGetSymbolAddress((void**)&khb, g_kh);
    cudaGetSymbolAddress((void**)&klb, g_kl);
    cudaGetSymbolAddress((void**)&vb,  g_vr);
    cudaGetSymbolAddress((void**)&ohb, g_oh);
    cudaGetSymbolAddress((void**)&olb, g_ol);
    cudaGetSymbolAddress((void**)&xhb, g_xh);
    cudaGetSymbolAddress((void**)&xlb, g_xl);
    cudaGetSymbolAddress((void**)&wqh, g_wqh);
    cudaGetSymbolAddress((void**)&wql, g_wql);
    cudaGetSymbolAddress((void**)&woh, g_woh);
    cudaGetSymbolAddress((void**)&wol, g_wol);

    cudaFuncSetAttribute(gemm_bf16p, cudaFuncAttributeMaxDynamicSharedMemorySize,
                         GEMM_SMEM);
    cudaFuncSetAttribute(attn_tc, cudaFuncAttributeMaxDynamicSharedMemorySize,
                         ATT_SMEM);

    // 0) convert inputs to bf16 hi/lo
    cvt_bf<<<2048, 256>>>(x, xhb, xlb, ROWS * DIM / 2);
    cvt_bf<<<1024, 256>>>(w_qkv, wqh, wql, QKV_E * DIM / 2);
    cvt_bf<<<512, 256>>>(w_out, woh, wol, DIM * DIM / 2);

    // 1) QKV projection with split epilogue (q fp32, k bf16hl, v rounded)
    {
        dim3 grid(QKV_E / 128, ROWS / 128);
        gemm_bf16p<<<grid, 256, GEMM_SMEM>>>(xhb, xlb, wqh, wql,
                                             nullptr, ROWS, QKV_E, DIM, 1,
                                             qb, khb, klb, vb);
    }
    // 2) fused attention -> bf16 hi/lo O
    {
        dim3 grid(SEQ / 128, NH, BATCH);
        attn_tc<<<grid, 128, ATT_SMEM>>>(qb, khb, klb, vb, ohb, olb);
    }
    // 3) output projection -> fp32 out
    {
        dim3 grid(DIM / 128, ROWS / 128);
        gemm_bf16p<<<grid, 256, GEMM_SMEM>>>(ohb, olb, woh, wol,
                                             out, ROWS, DIM, DIM, 0,
                                             nullptr, nullptr, nullptr, nullptr);
    }
}

// round 13
// speedup vs baseline: 1.0454x; 1.0454x over previous
#include <cuda_runtime.h>
#include <math_constants.h>

// Problem constants
#define BATCH 4
#define SEQ   2048
#define DIM   512
#define NH    8
#define HD    64
#define QKV_E (3 * DIM)      // 1536
#define ROWS  (BATCH * SEQ)  // 8192

// ---------------------------------------------------------------------------
// Scratch (allocation-free rule: __device__ globals). Word = unsigned (bf16x2).
// ---------------------------------------------------------------------------
__device__ float    g_q  [(size_t)ROWS * DIM];        // Q fp32, row-major [b*s, 512]
__device__ unsigned g_kh [(size_t)ROWS * DIM / 2];    // K bf16 hi, head-major [b,h,s,32w]
__device__ unsigned g_kl [(size_t)ROWS * DIM / 2];    // K bf16 lo
__device__ float    g_vr [(size_t)ROWS * DIM];        // V fp32 (tf32-rounded), head-major
__device__ unsigned g_oh [(size_t)ROWS * DIM / 2];    // attn out bf16 hi, row-major words
__device__ unsigned g_ol [(size_t)ROWS * DIM / 2];    // attn out bf16 lo
__device__ unsigned g_xh [(size_t)ROWS * DIM / 2];    // x bf16 hi
__device__ unsigned g_xl [(size_t)ROWS * DIM / 2];    // x bf16 lo
__device__ unsigned g_wqh[(size_t)QKV_E * DIM / 2];   // w_qkv bf16 hi
__device__ unsigned g_wql[(size_t)QKV_E * DIM / 2];
__device__ unsigned g_woh[(size_t)DIM * DIM / 2];     // w_out bf16 hi
__device__ unsigned g_wol[(size_t)DIM * DIM / 2];

// ---------------------------------------------------------------------------
// helpers
// ---------------------------------------------------------------------------
__device__ __forceinline__ unsigned f2tf(float f) {   // round-to-nearest tf32 bits
    unsigned r;
    asm("cvt.rna.tf32.f32 %0, %1;" : "=r"(r) : "f"(f));
    return r;
}
__device__ __forceinline__ unsigned bfpack(float f_even, float f_odd) {
    unsigned r;
    asm("cvt.rn.bf16x2.f32 %0, %1, %2;" : "=r"(r) : "f"(f_odd), "f"(f_even));
    return r;
}
__device__ __forceinline__ unsigned bflo(float f_even, float f_odd, unsigned h) {
    float r0 = f_even - __uint_as_float(h << 16);
    float r1 = f_odd  - __uint_as_float(h & 0xffff0000u);
    return bfpack(r0, r1);
}
__device__ __forceinline__ void mma_bf16(float c[4], const unsigned a[4],
                                         unsigned b0, unsigned b1) {
    asm volatile(
        "mma.sync.aligned.m16n8k16.row.col.f32.bf16.bf16.f32 "
        "{%0,%1,%2,%3}, {%4,%5,%6,%7}, {%8,%9}, {%0,%1,%2,%3};"
        : "+f"(c[0]), "+f"(c[1]), "+f"(c[2]), "+f"(c[3])
        : "r"(a[0]), "r"(a[1]), "r"(a[2]), "r"(a[3]), "r"(b0), "r"(b1));
}
__device__ __forceinline__ void mma_tf32(float c[4], const unsigned a[4],
                                         unsigned b0, unsigned b1) {
    asm volatile(
        "mma.sync.aligned.m16n8k8.row.col.f32.tf32.tf32.f32 "
        "{%0,%1,%2,%3}, {%4,%5,%6,%7}, {%8,%9}, {%0,%1,%2,%3};"
        : "+f"(c[0]), "+f"(c[1]), "+f"(c[2]), "+f"(c[3])
        : "r"(a[0]), "r"(a[1]), "r"(a[2]), "r"(a[3]), "r"(b0), "r"(b1));
}
__device__ __forceinline__ void cp16(unsigned sdst, const void* gsrc) {
    asm volatile("cp.async.cg.shared.global [%0], [%1], 16;"
                 :: "r"(sdst), "l"(gsrc) : "memory");
}
__device__ __forceinline__ void cp_commit() {
    asm volatile("cp.async.commit_group;" ::: "memory");
}
__device__ __forceinline__ void cp_wait1() {
    asm volatile("cp.async.wait_group 1;" ::: "memory");
}

// ---------------------------------------------------------------------------
// convert pass: fp32 -> bf16 hi/lo word arrays
// ---------------------------------------------------------------------------
__global__ void cvt_bf(const float* __restrict__ s, unsigned* __restrict__ h,
                       unsigned* __restrict__ l, int npairs)
{
    for (int i = blockIdx.x * blockDim.x + threadIdx.x; i < npairs;
         i += gridDim.x * blockDim.x) {
        float2 v = reinterpret_cast<const float2*>(s)[i];
        unsigned hi = bfpack(v.x, v.y);
        h[i] = hi;
        l[i] = bflo(v.x, v.y, hi);
    }
}

// ---------------------------------------------------------------------------
// bf16x3 GEMM from pre-split bf16 operands, cp.async double-buffered.
// C[M,N] = A[M,K] * W[N,K]^T. CTA 128x128, 256 threads = 8 warps (4 m x 2 n);
// each warp: 32 rows (2 m16) x 64 cols (8 n8). k-step 32.
// PASS-MAJOR inner loop: hh over all nt, then hl, then lh -> accumulator
// reuse distance 16 MMAs (covers HMMA latency).
// mode 0: plain fp32 C. mode 1: QKV split epilogue (q fp32 / k bf16hl / v rnd).
// ---------------------------------------------------------------------------
#define GLA 20                 // words per 32-bf16 row (16 data + 4 pad)
#define GSTG 10240             // words per stage: (128+128+128+128)*20
#define GEMM_SMEM (2 * GSTG * 4)   // 81920 B

__global__ __launch_bounds__(256, 2) void gemm_bf16p(
    const unsigned* __restrict__ Ah, const unsigned* __restrict__ Al,
    const unsigned* __restrict__ Wh, const unsigned* __restrict__ Wl,
    float* __restrict__ C, int M, int N, int K, int mode,
    float* __restrict__ qout, unsigned* __restrict__ khw,
    unsigned* __restrict__ klw, float* __restrict__ vrw)
{
    extern __shared__ __align__(16) unsigned smem_u[];
    const unsigned sb = (unsigned)__cvta_generic_to_shared(smem_u);

    const int tid  = threadIdx.x;
    const int warp = tid >> 5;
    const int wm   = warp >> 1;        // 0..3 (m direction)
    const int wn   = warp & 1;         // 0..1 (n direction)
    const int lane = tid & 31;
    const int g    = lane >> 2;
    const int c    = lane & 3;
    const int m0   = blockIdx.y * 128;
    const int n0   = blockIdx.x * 128;
    const int Kw   = K >> 1;

    auto issue = [&](int k0, int buf) {
        unsigned base = sb + buf * GSTG * 4;
        int k0w = k0 >> 1;
#pragma unroll
        for (int it = 0; it < 8; it++) {
            int cid = it * 256 + tid;       // 0..2047
            int row = (cid >> 2) & 127;
            int ch  = cid & 3;
            if (cid < 512) {
                cp16(base + (row * GLA + ch * 4) * 4,
                     Ah + (size_t)(m0 + row) * Kw + k0w + ch * 4);
            } else if (cid < 1024) {
                cp16(base + (2560 + row * GLA + ch * 4) * 4,
                     Al + (size_t)(m0 + row) * Kw + k0w + ch * 4);
            } else if (cid < 1536) {
                cp16(base + (5120 + row * GLA + ch * 4) * 4,
                     Wh + (size_t)(n0 + row) * Kw + k0w + ch * 4);
            } else {
                cp16(base + (7680 + row * GLA + ch * 4) * 4,
                     Wl + (size_t)(n0 + row) * Kw + k0w + ch * 4);
            }
        }
    };

    float acc[2][8][4];
#pragma unroll
    for (int mt = 0; mt < 2; mt++)
#pragma unroll
        for (int nt = 0; nt < 8; nt++)
#pragma unroll
            for (int i = 0; i < 4; i++) acc[mt][nt][i] = 0.0f;

    const int NT = K / 32;    // 16
    issue(0, 0);  cp_commit();
    issue(32, 1); cp_commit();

    for (int kt = 0; kt < NT; kt++) {
        cp_wait1();
        __syncthreads();
        const unsigned* bAh = smem_u + (kt & 1) * GSTG;
        const unsigned* bAl = bAh + 2560;
        const unsigned* bWh = bAh + 5120;
        const unsigned* bWl = bAh + 7680;

#pragma unroll
        for (int ks = 0; ks < 2; ks++) {
            unsigned ah[2][4], al[2][4];
#pragma unroll
            for (int mt = 0; mt < 2; mt++) {
                int rA = wm * 32 + mt * 16 + g;
                ah[mt][0] = bAh[rA * GLA + ks * 8 + c];
                ah[mt][1] = bAh[(rA + 8) * GLA + ks * 8 + c];
                ah[mt][2] = bAh[rA * GLA + ks * 8 + c + 4];
                ah[mt][3] = bAh[(rA + 8) * GLA + ks * 8 + c + 4];
                al[mt][0] = bAl[rA * GLA + ks * 8 + c];
                al[mt][1] = bAl[(rA + 8) * GLA + ks * 8 + c];
                al[mt][2] = bAl[rA * GLA + ks * 8 + c + 4];
                al[mt][3] = bAl[(rA + 8) * GLA + ks * 8 + c + 4];
            }
            // pass 1: hi*hi over all nt (acc reuse distance = 16 MMAs)
#pragma unroll
            for (int nt = 0; nt < 8; nt++) {
                int rB = wn * 64 + nt * 8 + g;
                unsigned b0 = bWh[rB * GLA + ks * 8 + c];
                unsigned b1 = bWh[rB * GLA + ks * 8 + c + 4];
                mma_bf16(acc[0][nt], ah[0], b0, b1);
                mma_bf16(acc[1][nt], ah[1], b0, b1);
            }
            // pass 2: hi*lo
#pragma unroll
            for (int nt = 0; nt < 8; nt++) {
                int rB = wn * 64 + nt * 8 + g;
                unsigned b0 = bWl[rB * GLA + ks * 8 + c];
                unsigned b1 = bWl[rB * GLA + ks * 8 + c + 4];
                mma_bf16(acc[0][nt], ah[0], b0, b1);
                mma_bf16(acc[1][nt], ah[1], b0, b1);
            }
            // pass 3: lo*hi
#pragma unroll
            for (int nt = 0; nt < 8; nt++) {
                int rB = wn * 64 + nt * 8 + g;
                unsigned b0 = bWh[rB * GLA + ks * 8 + c];
                unsigned b1 = bWh[rB * GLA + ks * 8 + c + 4];
                mma_bf16(acc[0][nt], al[0], b0, b1);
                mma_bf16(acc[1][nt], al[1], b0, b1);
            }
        }
        __syncthreads();
        if (kt + 2 < NT) issue((kt + 2) * 32, kt & 1);
        cp_commit();
    }

    // ---- epilogue (warp column base nb selects q/k/v region in mode 1) ----
    const int nb = n0 + wn * 64;
    if (mode == 0) {
#pragma unroll
        for (int mt = 0; mt < 2; mt++) {
            int r0 = m0 + wm * 32 + mt * 16 + g;
#pragma unroll
            for (int nt = 0; nt < 8; nt++) {
                *reinterpret_cast<float2*>(C + (size_t)r0 * N + nb + nt * 8 + 2 * c) =
                    make_float2(acc[mt][nt][0], acc[mt][nt][1]);
                *reinterpret_cast<float2*>(C + (size_t)(r0 + 8) * N + nb + nt * 8 + 2 * c) =
                    make_float2(acc[mt][nt][2], acc[mt][nt][3]);
            }
        }
    } else if (nb < DIM) {
        // q region: plain fp32 into g_q
#pragma unroll
        for (int mt = 0; mt < 2; mt++) {
            int r0 = m0 + wm * 32 + mt * 16 + g;
#pragma unroll
            for (int nt = 0; nt < 8; nt++) {
                *reinterpret_cast<float2*>(qout + (size_t)r0 * DIM + nb + nt * 8 + 2 * c) =
                    make_float2(acc[mt][nt][0], acc[mt][nt][1]);
                *reinterpret_cast<float2*>(qout + (size_t)(r0 + 8) * DIM + nb + nt * 8 + 2 * c) =
                    make_float2(acc[mt][nt][2], acc[mt][nt][3]);
            }
        }
    } else if (nb < 2 * DIM) {
        // k region: bf16 hi/lo, head-major [b, h, s, 32 words]
        int hh = (nb - DIM) >> 6;
        size_t rowb = ((size_t)((m0 >> 11) * NH + hh)) * SEQ + (m0 & 2047);
#pragma unroll
        for (int mt = 0; mt < 2; mt++) {
            int lr = wm * 32 + mt * 16 + g;
#pragma unroll
            for (int nt = 0; nt < 8; nt++) {
                unsigned h0 = bfpack(acc[mt][nt][0], acc[mt][nt][1]);
                size_t i0 = (rowb + lr) * 32 + nt * 4 + c;
                khw[i0] = h0;
                klw[i0] = bflo(acc[mt][nt][0], acc[mt][nt][1], h0);
                unsigned h1 = bfpack(acc[mt][nt][2], acc[mt][nt][3]);
                size_t i1 = (rowb + lr + 8) * 32 + nt * 4 + c;
                khw[i1] = h1;
                klw[i1] = bflo(acc[mt][nt][2], acc[mt][nt][3], h1);
            }
        }
    } else {
        // v region: tf32-rounded fp32, head-major [b, h, s, 64]
        int hh = (nb - 2 * DIM) >> 6;
        size_t rowb = ((size_t)((m0 >> 11) * NH + hh)) * SEQ + (m0 & 2047);
#pragma unroll
        for (int mt = 0; mt < 2; mt++) {
            int lr = wm * 32 + mt * 16 + g;
#pragma unroll
            for (int nt = 0; nt < 8; nt++) {
                *reinterpret_cast<float2*>(vrw + (rowb + lr) * HD + nt * 8 + 2 * c) =
                    make_float2(__uint_as_float(f2tf(acc[mt][nt][0])),
                                __uint_as_float(f2tf(acc[mt][nt][1])));
                *reinterpret_cast<float2*>(vrw + (rowb + lr + 8) * HD + nt * 8 + 2 * c) =
                    make_float2(__uint_as_float(f2tf(acc[mt][nt][2])),
                                __uint_as_float(f2tf(acc[mt][nt][3])));
            }
        }
    }
}

// ---------------------------------------------------------------------------
// Fused attention (round-9 design, best measured): S = QK^T (bf16x3 from
// precomputed K hi/lo), P = round_tf32(exp(S-24)) through SMEM, O += P V
// (tf32, V pre-rounded). cp.async double-buffered K/V ring. 128 queries/CTA,
// 4 warps x 2 m16-tiles, key tiles of 64.
// ---------------------------------------------------------------------------
#define LDP 68                  // sP stride (floats)
#define LDKW 36                 // K stage row stride (words: 32 data + 4 pad)
#define LDV 72                  // V stage row stride (words)
#define SP_W (128 * LDP)        // 8704 words
#define ATT_STG (64 * LDKW * 2 + 64 * LDV)   // 9216 words per stage
#define ATT_SMEM ((SP_W + 2 * ATT_STG) * 4)  // 108544 B

__global__ __launch_bounds__(128, 2) void attn_tc(
    const float* __restrict__ qg, const unsigned* __restrict__ khw,
    const unsigned* __restrict__ klw, const float* __restrict__ vr,
    unsigned* __restrict__ ohw, unsigned* __restrict__ olw)
{
    extern __shared__ __align__(16) unsigned smem_u[];
    const unsigned sb = (unsigned)__cvta_generic_to_shared(smem_u);
    float* sPf = reinterpret_cast<float*>(smem_u);
    unsigned* sPu = smem_u;

    const int tid  = threadIdx.x;
    const int warp = tid >> 5;
    const int lane = tid & 31;
    const int g    = lane >> 2;
    const int c    = lane & 3;

    const int h  = blockIdx.y;
    const int b  = blockIdx.z;
    const int q0 = blockIdx.x * 128;
    const int bh8 = b * NH + h;

    auto issue = [&](int kt, int stage) {
        unsigned base = sb + (SP_W + stage * ATT_STG) * 4;
        size_t tb = (size_t)bh8 * SEQ + kt * 64;   // head-major row base
#pragma unroll
        for (int it = 0; it < 16; it++) {
            int cid = it * 128 + tid;
            if (cid < 512) {
                int row = cid >> 3, ch = cid & 7;
                cp16(base + (row * LDKW + ch * 4) * 4, khw + (tb + row) * 32 + ch * 4);
            } else if (cid < 1024) {
                int c2 = cid - 512; int row = c2 >> 3, ch = c2 & 7;
                cp16(base + (64 * LDKW + row * LDKW + ch * 4) * 4,
                     klw + (tb + row) * 32 + ch * 4);
            } else {
                int c2 = cid - 1024; int row = c2 >> 4, ch = c2 & 15;
                cp16(base + (128 * LDKW + row * LDV + ch * 4) * 4,
                     vr + (tb + row) * HD + ch * 4);
            }
        }
    };

    // prologue: start loading key tiles 0 and 1 immediately
    issue(0, 0); cp_commit();
    issue(1, 1); cp_commit();

    // ---- stage Q tile (128x64 fp32) into sP, build bf16 hi/lo fragments ----
    const float* qbase = qg + (size_t)b * SEQ * DIM + h * HD;
#pragma unroll
    for (int it = 0; it < 16; it++) {
        int idx = it * 128 + tid;
        int row = idx >> 4;
        int seg = (idx & 15) * 4;
        *reinterpret_cast<float4*>(&sPf[row * LDP + seg]) =
            *reinterpret_cast<const float4*>(qbase + (size_t)(q0 + row) * DIM + seg);
    }
    __syncthreads();

    unsigned qh[2][4][4], ql[2][4][4];
#pragma unroll
    for (int mt = 0; mt < 2; mt++) {
        int r0 = warp * 32 + mt * 16 + g;
#pragma unroll
        for (int ks = 0; ks < 4; ks++) {
            float2 e00 = *reinterpret_cast<float2*>(&sPf[r0 * LDP + ks * 16 + 2 * c]);
            float2 e10 = *reinterpret_cast<float2*>(&sPf[(r0 + 8) * LDP + ks * 16 + 2 * c]);
            float2 e01 = *reinterpret_cast<float2*>(&sPf[r0 * LDP + ks * 16 + 2 * c + 8]);
            float2 e11 = *reinterpret_cast<float2*>(&sPf[(r0 + 8) * LDP + ks * 16 + 2 * c + 8]);
            qh[mt][ks][0] = bfpack(e00.x, e00.y);
            qh[mt][ks][1] = bfpack(e10.x, e10.y);
            qh[mt][ks][2] = bfpack(e01.x, e01.y);
            qh[mt][ks][3] = bfpack(e11.x, e11.y);
            ql[mt][ks][0] = bflo(e00.x, e00.y, qh[mt][ks][0]);
            ql[mt][ks][1] = bflo(e10.x, e10.y, qh[mt][ks][1]);
            ql[mt][ks][2] = bflo(e01.x, e01.y, qh[mt][ks][2]);
            ql[mt][ks][3] = bflo(e11.x, e11.y, qh[mt][ks][3]);
        }
    }

    float O[2][8][4];
#pragma unroll
    for (int mt = 0; mt < 2; mt++)
#pragma unroll
        for (int nt = 0; nt < 8; nt++)
#pragma unroll
            for (int i = 0; i < 4; i++) O[mt][nt][i] = 0.0f;
    float lsum[2][2] = {{0.0f, 0.0f}, {0.0f, 0.0f}};

    for (int kt = 0; kt < SEQ / 64; kt++) {
        cp_wait1();
        __syncthreads();
        const unsigned* bKh = smem_u + SP_W + (kt & 1) * ATT_STG;
        const unsigned* bKl = bKh + 64 * LDKW;
        const unsigned* bV  = bKh + 128 * LDKW;

        // ---- S = Q K^T (bf16x3), nt-pairs for 4-way accumulator ILP ----
#pragma unroll
        for (int np = 0; np < 4; np++) {
            float s4[2][2][4];   // [nn][mt][4]
#pragma unroll
            for (int nn = 0; nn < 2; nn++)
#pragma unroll
                for (int mt = 0; mt < 2; mt++)
#pragma unroll
                    for (int i = 0; i < 4; i++) s4[nn][mt][i] = 0.0f;
#pragma unroll
            for (int ks = 0; ks < 4; ks++) {
                unsigned bh0[2], bh1[2], bl0[2], bl1[2];
#pragma unroll
                for (int nn = 0; nn < 2; nn++) {
                    int rB = (np * 2 + nn) * 8 + g;
                    bh0[nn] = bKh[rB * LDKW + ks * 8 + c];
                    bh1[nn] = bKh[rB * LDKW + ks * 8 + c + 4];
                    bl0[nn] = bKl[rB * LDKW + ks * 8 + c];
                    bl1[nn] = bKl[rB * LDKW + ks * 8 + c + 4];
                }
                // pass-major: dependent-MMA gap of 4
#pragma unroll
                for (int nn = 0; nn < 2; nn++)
#pragma unroll
                    for (int mt = 0; mt < 2; mt++)
                        mma_bf16(s4[nn][mt], qh[mt][ks], bh0[nn], bh1[nn]);
#pragma unroll
                for (int nn = 0; nn < 2; nn++)
#pragma unroll
                    for (int mt = 0; mt < 2; mt++)
                        mma_bf16(s4[nn][mt], qh[mt][ks], bl0[nn], bl1[nn]);
#pragma unroll
                for (int nn = 0; nn < 2; nn++)
#pragma unroll
                    for (int mt = 0; mt < 2; mt++)
                        mma_bf16(s4[nn][mt], ql[mt][ks], bh0[nn], bh1[nn]);
            }
            // P = exp(S - 24), rounded to tf32 (lsum uses the rounded value)
#pragma unroll
            for (int nn = 0; nn < 2; nn++) {
                int nt = np * 2 + nn;
#pragma unroll
                for (int mt = 0; mt < 2; mt++) {
                    int r0 = warp * 32 + mt * 16 + g;
                    unsigned r00 = f2tf(__expf(s4[nn][mt][0] - 24.0f));
                    unsigned r01 = f2tf(__expf(s4[nn][mt][1] - 24.0f));
                    unsigned r10 = f2tf(__expf(s4[nn][mt][2] - 24.0f));
                    unsigned r11 = f2tf(__expf(s4[nn][mt][3] - 24.0f));
                    lsum[mt][0] += __uint_as_float(r00) + __uint_as_float(r01);
                    lsum[mt][1] += __uint_as_float(r10) + __uint_as_float(r11);
                    *reinterpret_cast<uint2*>(&sPu[r0 * LDP + nt * 8 + 2 * c]) =
                        make_uint2(r00, r01);
                    *reinterpret_cast<uint2*>(&sPu[(r0 + 8) * LDP + nt * 8 + 2 * c]) =
                        make_uint2(r10, r11);
                }
            }
        }
        __syncwarp();   // each warp reads back only its own sP rows

        // ---- O += P V (tf32); V fragments shared across mt ----
#pragma unroll
        for (int kk = 0; kk < 8; kk++) {
            unsigned pa[2][4];
#pragma unroll
            for (int mt = 0; mt < 2; mt++) {
                int r0 = warp * 32 + mt * 16 + g;
                pa[mt][0] = sPu[r0 * LDP + kk * 8 + c];
                pa[mt][1] = sPu[(r0 + 8) * LDP + kk * 8 + c];
                pa[mt][2] = sPu[r0 * LDP + kk * 8 + c + 4];
                pa[mt][3] = sPu[(r0 + 8) * LDP + kk * 8 + c + 4];
            }
#pragma unroll
            for (int nt = 0; nt < 8; nt++) {
                unsigned vh0 = bV[(kk * 8 + c) * LDV + nt * 8 + g];
                unsigned vh1 = bV[(kk * 8 + c + 4) * LDV + nt * 8 + g];
                mma_tf32(O[0][nt], pa[0], vh0, vh1);
                mma_tf32(O[1][nt], pa[1], vh0, vh1);
            }
        }

        __syncthreads();    // all warps done with this stage's K/V
        if (kt + 2 < SEQ / 64) issue(kt + 2, kt & 1);
        cp_commit();
    }

    // ---- normalize and store as bf16 hi/lo (out-proj A operand) ----
#pragma unroll
    for (int mt = 0; mt < 2; mt++)
#pragma unroll
        for (int i = 0; i < 2; i++) {
            lsum[mt][i] += __shfl_xor_sync(0xffffffffu, lsum[mt][i], 1);
            lsum[mt][i] += __shfl_xor_sync(0xffffffffu, lsum[mt][i], 2);
        }

#pragma unroll
    for (int mt = 0; mt < 2; mt++) {
        const float inv0 = 1.0f / lsum[mt][0];
        const float inv1 = 1.0f / lsum[mt][1];
        int qr = q0 + warp * 32 + mt * 16 + g;
        size_t r0w = ((size_t)b * SEQ + qr) * (DIM / 2) + h * (HD / 2);
        size_t r1w = ((size_t)b * SEQ + qr + 8) * (DIM / 2) + h * (HD / 2);
#pragma unroll
        for (int nt = 0; nt < 8; nt++) {
            float o0 = O[mt][nt][0] * inv0, o1 = O[mt][nt][1] * inv0;
            float o2 = O[mt][nt][2] * inv1, o3 = O[mt][nt][3] * inv1;
            unsigned h0 = bfpack(o0, o1);
            ohw[r0w + nt * 4 + c] = h0;
            olw[r0w + nt * 4 + c] = bflo(o0, o1, h0);
            unsigned h1 = bfpack(o2, o3);
            ohw[r1w + nt * 4 + c] = h1;
            olw[r1w + nt * 4 + c] = bflo(o2, o3, h1);
        }
    }
}

// ---------------------------------------------------------------------------
extern "C" void kernel_launch(void* const* d_in, const int* in_sizes, int n_in,
                              void* d_out, int out_size)
{
    const float* x     = (const float*)d_in[0];  // [4, 2048, 512]
    const float* w_qkv = (const float*)d_in[1];  // [1536, 512]
    const float* w_out = (const float*)d_in[2];  // [512, 512]
    float* out = (float*)d_out;                  // [4, 2048, 512]

    float *qb, *vb;
    unsigned *khb, *klb, *ohb, *olb, *xhb, *xlb, *wqh, *wql, *woh, *wol;
    cudaGetSymbolAddress((void**)&qb,  g_q);
    cudaGetSymbolAddress((void**)&khb, g_kh);
    cudaGetSymbolAddress((void**)&klb, g_kl);
    cudaGetSymbolAddress((void**)&vb,  g_vr);
    cudaGetSymbolAddress((void**)&ohb, g_oh);
    cudaGetSymbolAddress((void**)&olb, g_ol);
    cudaGetSymbolAddress((void**)&xhb, g_xh);
    cudaGetSymbolAddress((void**)&xlb, g_xl);
    cudaGetSymbolAddress((void**)&wqh, g_wqh);
    cudaGetSymbolAddress((void**)&wql, g_wql);
    cudaGetSymbolAddress((void**)&woh, g_woh);
    cudaGetSymbolAddress((void**)&wol, g_wol);

    cudaFuncSetAttribute(gemm_bf16p, cudaFuncAttributeMaxDynamicSharedMemorySize,
                         GEMM_SMEM);
    cudaFuncSetAttribute(attn_tc, cudaFuncAttributeMaxDynamicSharedMemorySize,
                         ATT_SMEM);

    // 0) convert inputs to bf16 hi/lo
    cvt_bf<<<2048, 256>>>(x, xhb, xlb, ROWS * DIM / 2);
    cvt_bf<<<1024, 256>>>(w_qkv, wqh, wql, QKV_E * DIM / 2);
    cvt_bf<<<512, 256>>>(w_out, woh, wol, DIM * DIM / 2);

    // 1) QKV projection with split epilogue (q fp32, k bf16hl, v rounded)
    {
        dim3 grid(QKV_E / 128, ROWS / 128);
        gemm_bf16p<<<grid, 256, GEMM_SMEM>>>(xhb, xlb, wqh, wql,
                                             nullptr, ROWS, QKV_E, DIM, 1,
                                             qb, khb, klb, vb);
    }
    // 2) fused attention -> bf16 hi/lo O
    {
        dim3 grid(SEQ / 128, NH, BATCH);
        attn_tc<<<grid, 128, ATT_SMEM>>>(qb, khb, klb, vb, ohb, olb);
    }
    // 3) output projection -> fp32 out
    {
        dim3 grid(DIM / 128, ROWS / 128);
        gemm_bf16p<<<grid, 256, GEMM_SMEM>>>(ohb, olb, woh, wol,
                                             out, ROWS, DIM, DIM, 0,
                                             nullptr, nullptr, nullptr, nullptr);
    }
}

// round 17
// speedup vs baseline: 1.1600x; 1.1096x over previous
#include <cuda_runtime.h>
#include <math_constants.h>
#include <cstdint>

// Problem constants
#define BATCH 4
#define SEQ   2048
#define DIM   512
#define NH    8
#define HD    64
#define QKV_E (3 * DIM)      // 1536
#define ROWS  (BATCH * SEQ)  // 8192

// ---------------------------------------------------------------------------
// Scratch (allocation-free rule: __device__ globals). Word = unsigned (bf16x2).
// ---------------------------------------------------------------------------
__device__ float    g_q  [(size_t)ROWS * DIM];        // Q fp32, row-major [b*s, 512]
__device__ unsigned g_kh [(size_t)ROWS * DIM / 2];    // K bf16 hi, head-major [b,h,s,32w]
__device__ unsigned g_kl [(size_t)ROWS * DIM / 2];    // K bf16 lo
__device__ unsigned short g_v16[(size_t)ROWS * DIM];  // V fp16, [b,h, s/2, d, s&1]
__device__ unsigned g_oh [(size_t)ROWS * DIM / 2];    // attn out bf16 hi, row-major words
__device__ unsigned g_ol [(size_t)ROWS * DIM / 2];    // attn out bf16 lo
__device__ unsigned g_xh [(size_t)ROWS * DIM / 2];    // x bf16 hi
__device__ unsigned g_xl [(size_t)ROWS * DIM / 2];    // x bf16 lo
__device__ unsigned g_wqh[(size_t)QKV_E * DIM / 2];   // w_qkv bf16 hi
__device__ unsigned g_wql[(size_t)QKV_E * DIM / 2];
__device__ unsigned g_woh[(size_t)DIM * DIM / 2];     // w_out bf16 hi
__device__ unsigned g_wol[(size_t)DIM * DIM / 2];

// ---------------------------------------------------------------------------
// helpers
// ---------------------------------------------------------------------------
__device__ __forceinline__ unsigned bfpack(float f_even, float f_odd) {
    unsigned r;
    asm("cvt.rn.bf16x2.f32 %0, %1, %2;" : "=r"(r) : "f"(f_odd), "f"(f_even));
    return r;
}
__device__ __forceinline__ unsigned bflo(float f_even, float f_odd, unsigned h) {
    float r0 = f_even - __uint_as_float(h << 16);
    float r1 = f_odd  - __uint_as_float(h & 0xffff0000u);
    return bfpack(r0, r1);
}
__device__ __forceinline__ unsigned h2pack(float lo, float hi) {  // lo -> low half
    unsigned r;
    asm("cvt.rn.f16x2.f32 %0, %1, %2;" : "=r"(r) : "f"(hi), "f"(lo));
    return r;
}
__device__ __forceinline__ unsigned hmax2(unsigned a, unsigned b) {
    unsigned r;
    asm("max.f16x2 %0, %1, %2;" : "=r"(r) : "r"(a), "r"(b));
    return r;
}
__device__ __forceinline__ float h2lo(unsigned u) {
    float f;
    asm("{.reg .b16 l, h; mov.b32 {l, h}, %1; cvt.f32.f16 %0, l;}" : "=f"(f) : "r"(u));
    return f;
}
__device__ __forceinline__ float h2hi(unsigned u) {
    float f;
    asm("{.reg .b16 l, h; mov.b32 {l, h}, %1; cvt.f32.f16 %0, h;}" : "=f"(f) : "r"(u));
    return f;
}
__device__ __forceinline__ unsigned short f2h(float f) {
    unsigned short r;
    asm("cvt.rn.f16.f32 %0, %1;" : "=h"(r) : "f"(f));
    return r;
}
__device__ __forceinline__ void mma_bf16(float c[4], const unsigned a[4],
                                         unsigned b0, unsigned b1) {
    asm volatile(
        "mma.sync.aligned.m16n8k16.row.col.f32.bf16.bf16.f32 "
        "{%0,%1,%2,%3}, {%4,%5,%6,%7}, {%8,%9}, {%0,%1,%2,%3};"
        : "+f"(c[0]), "+f"(c[1]), "+f"(c[2]), "+f"(c[3])
        : "r"(a[0]), "r"(a[1]), "r"(a[2]), "r"(a[3]), "r"(b0), "r"(b1));
}
__device__ __forceinline__ void mma_f16(float c[4], const unsigned a[4],
                                        unsigned b0, unsigned b1) {
    asm volatile(
        "mma.sync.aligned.m16n8k16.row.col.f32.f16.f16.f32 "
        "{%0,%1,%2,%3}, {%4,%5,%6,%7}, {%8,%9}, {%0,%1,%2,%3};"
        : "+f"(c[0]), "+f"(c[1]), "+f"(c[2]), "+f"(c[3])
        : "r"(a[0]), "r"(a[1]), "r"(a[2]), "r"(a[3]), "r"(b0), "r"(b1));
}
__device__ __forceinline__ void cp16(unsigned sdst, const void* gsrc) {
    asm volatile("cp.async.cg.shared.global [%0], [%1], 16;"
                 :: "r"(sdst), "l"(gsrc) : "memory");
}
__device__ __forceinline__ void cp_commit() {
    asm volatile("cp.async.commit_group;" ::: "memory");
}
__device__ __forceinline__ void cp_wait1() {
    asm volatile("cp.async.wait_group 1;" ::: "memory");
}

// ---------------------------------------------------------------------------
// convert pass: fp32 -> bf16 hi/lo word arrays
// ---------------------------------------------------------------------------
__global__ void cvt_bf(const float* __restrict__ s, unsigned* __restrict__ h,
                       unsigned* __restrict__ l, int npairs)
{
    for (int i = blockIdx.x * blockDim.x + threadIdx.x; i < npairs;
         i += gridDim.x * blockDim.x) {
        float2 v = reinterpret_cast<const float2*>(s)[i];
        unsigned hi = bfpack(v.x, v.y);
        h[i] = hi;
        l[i] = bflo(v.x, v.y, hi);
    }
}

// ---------------------------------------------------------------------------
// bf16x3 GEMM from pre-split bf16 operands, cp.async double-buffered.
// C[M,N] = A[M,K] * W[N,K]^T. CTA 128x128, 256 threads = 8 warps (4 m x 2 n).
// mode 0: plain fp32 C. mode 1: QKV split epilogue (q fp32 / k bf16hl / v fp16).
// ---------------------------------------------------------------------------
#define GLA 20                 // words per 32-bf16 row (16 data + 4 pad)
#define GSTG 10240             // words per stage: (128+128+128+128)*20
#define GEMM_SMEM (2 * GSTG * 4)   // 81920 B

__global__ __launch_bounds__(256, 2) void gemm_bf16p(
    const unsigned* __restrict__ Ah, const unsigned* __restrict__ Al,
    const unsigned* __restrict__ Wh, const unsigned* __restrict__ Wl,
    float* __restrict__ C, int M, int N, int K, int mode,
    float* __restrict__ qout, unsigned* __restrict__ khw,
    unsigned* __restrict__ klw, unsigned short* __restrict__ v16)
{
    extern __shared__ __align__(16) unsigned smem_u[];
    const unsigned sb = (unsigned)__cvta_generic_to_shared(smem_u);

    const int tid  = threadIdx.x;
    const int warp = tid >> 5;
    const int wm   = warp >> 1;
    const int wn   = warp & 1;
    const int lane = tid & 31;
    const int g    = lane >> 2;
    const int c    = lane & 3;
    const int m0   = blockIdx.y * 128;
    const int n0   = blockIdx.x * 128;
    const int Kw   = K >> 1;

    auto issue = [&](int k0, int buf) {
        unsigned base = sb + buf * GSTG * 4;
        int k0w = k0 >> 1;
#pragma unroll
        for (int it = 0; it < 8; it++) {
            int cid = it * 256 + tid;
            int row = (cid >> 2) & 127;
            int ch  = cid & 3;
            if (cid < 512) {
                cp16(base + (row * GLA + ch * 4) * 4,
                     Ah + (size_t)(m0 + row) * Kw + k0w + ch * 4);
            } else if (cid < 1024) {
                cp16(base + (2560 + row * GLA + ch * 4) * 4,
                     Al + (size_t)(m0 + row) * Kw + k0w + ch * 4);
            } else if (cid < 1536) {
                cp16(base + (5120 + row * GLA + ch * 4) * 4,
                     Wh + (size_t)(n0 + row) * Kw + k0w + ch * 4);
            } else {
                cp16(base + (7680 + row * GLA + ch * 4) * 4,
                     Wl + (size_t)(n0 + row) * Kw + k0w + ch * 4);
            }
        }
    };

    float acc[2][8][4];
#pragma unroll
    for (int mt = 0; mt < 2; mt++)
#pragma unroll
        for (int nt = 0; nt < 8; nt++)
#pragma unroll
            for (int i = 0; i < 4; i++) acc[mt][nt][i] = 0.0f;

    const int NT = K / 32;
    issue(0, 0);  cp_commit();
    issue(32, 1); cp_commit();

    for (int kt = 0; kt < NT; kt++) {
        cp_wait1();
        __syncthreads();
        const unsigned* bAh = smem_u + (kt & 1) * GSTG;
        const unsigned* bAl = bAh + 2560;
        const unsigned* bWh = bAh + 5120;
        const unsigned* bWl = bAh + 7680;

#pragma unroll
        for (int ks = 0; ks < 2; ks++) {
            unsigned ah[2][4], al[2][4];
#pragma unroll
            for (int mt = 0; mt < 2; mt++) {
                int rA = wm * 32 + mt * 16 + g;
                ah[mt][0] = bAh[rA * GLA + ks * 8 + c];
                ah[mt][1] = bAh[(rA + 8) * GLA + ks * 8 + c];
                ah[mt][2] = bAh[rA * GLA + ks * 8 + c + 4];
                ah[mt][3] = bAh[(rA + 8) * GLA + ks * 8 + c + 4];
                al[mt][0] = bAl[rA * GLA + ks * 8 + c];
                al[mt][1] = bAl[(rA + 8) * GLA + ks * 8 + c];
                al[mt][2] = bAl[rA * GLA + ks * 8 + c + 4];
                al[mt][3] = bAl[(rA + 8) * GLA + ks * 8 + c + 4];
            }
#pragma unroll
            for (int nt = 0; nt < 8; nt++) {
                int rB = wn * 64 + nt * 8 + g;
                unsigned bh0 = bWh[rB * GLA + ks * 8 + c];
                unsigned bh1 = bWh[rB * GLA + ks * 8 + c + 4];
                unsigned bl0 = bWl[rB * GLA + ks * 8 + c];
                unsigned bl1 = bWl[rB * GLA + ks * 8 + c + 4];
                mma_bf16(acc[0][nt], ah[0], bh0, bh1);
                mma_bf16(acc[1][nt], ah[1], bh0, bh1);
                mma_bf16(acc[0][nt], ah[0], bl0, bl1);
                mma_bf16(acc[1][nt], ah[1], bl0, bl1);
                mma_bf16(acc[0][nt], al[0], bh0, bh1);
                mma_bf16(acc[1][nt], al[1], bh0, bh1);
            }
        }
        __syncthreads();
        if (kt + 2 < NT) issue((kt + 2) * 32, kt & 1);
        cp_commit();
    }

    // ---- epilogue ----
    const int nb = n0 + wn * 64;
    if (mode == 0) {
#pragma unroll
        for (int mt = 0; mt < 2; mt++) {
            int r0 = m0 + wm * 32 + mt * 16 + g;
#pragma unroll
            for (int nt = 0; nt < 8; nt++) {
                *reinterpret_cast<float2*>(C + (size_t)r0 * N + nb + nt * 8 + 2 * c) =
                    make_float2(acc[mt][nt][0], acc[mt][nt][1]);
                *reinterpret_cast<float2*>(C + (size_t)(r0 + 8) * N + nb + nt * 8 + 2 * c) =
                    make_float2(acc[mt][nt][2], acc[mt][nt][3]);
            }
        }
    } else if (nb < DIM) {
#pragma unroll
        for (int mt = 0; mt < 2; mt++) {
            int r0 = m0 + wm * 32 + mt * 16 + g;
#pragma unroll
            for (int nt = 0; nt < 8; nt++) {
                *reinterpret_cast<float2*>(qout + (size_t)r0 * DIM + nb + nt * 8 + 2 * c) =
                    make_float2(acc[mt][nt][0], acc[mt][nt][1]);
                *reinterpret_cast<float2*>(qout + (size_t)(r0 + 8) * DIM + nb + nt * 8 + 2 * c) =
                    make_float2(acc[mt][nt][2], acc[mt][nt][3]);
            }
        }
    } else if (nb < 2 * DIM) {
        // k region: bf16 hi/lo, head-major [b, h, s, 32 words]
        int hh = (nb - DIM) >> 6;
        size_t rowb = ((size_t)((m0 >> 11) * NH + hh)) * SEQ + (m0 & 2047);
#pragma unroll
        for (int mt = 0; mt < 2; mt++) {
            int lr = wm * 32 + mt * 16 + g;
#pragma unroll
            for (int nt = 0; nt < 8; nt++) {
                unsigned h0 = bfpack(acc[mt][nt][0], acc[mt][nt][1]);
                size_t i0 = (rowb + lr) * 32 + nt * 4 + c;
                khw[i0] = h0;
                klw[i0] = bflo(acc[mt][nt][0], acc[mt][nt][1], h0);
                unsigned h1 = bfpack(acc[mt][nt][2], acc[mt][nt][3]);
                size_t i1 = (rowb + lr + 8) * 32 + nt * 4 + c;
                khw[i1] = h1;
                klw[i1] = bflo(acc[mt][nt][2], acc[mt][nt][3], h1);
            }
        }
    } else {
        // v region: fp16, layout [bh][s/2][d][s&1]  (k-pair packed words)
        int hh = (nb - 2 * DIM) >> 6;
        int bh = (m0 >> 11) * NH + hh;
#pragma unroll
        for (int mt = 0; mt < 2; mt++) {
            int s0 = (m0 & 2047) + wm * 32 + mt * 16 + g;   // rows s0, s0+8
#pragma unroll
            for (int nt = 0; nt < 8; nt++) {
                int d = nt * 8 + 2 * c;
                size_t b0 = ((size_t)bh * 1024 + (s0 >> 1)) * 128 + d * 2 + (s0 & 1);
                v16[b0]     = f2h(acc[mt][nt][0]);
                v16[b0 + 2] = f2h(acc[mt][nt][1]);
                int s1 = s0 + 8;
                size_t b1 = ((size_t)bh * 1024 + (s1 >> 1)) * 128 + d * 2 + (s1 & 1);
                v16[b1]     = f2h(acc[mt][nt][2]);
                v16[b1 + 2] = f2h(acc[mt][nt][3]);
            }
        }
    }
}

// ---------------------------------------------------------------------------
// Fused attention: S = QK^T (bf16x3), flash running-max softmax, P packed in
// REGISTERS as fp16 A-fragments (QK accumulator layout == f16 A k-pair layout,
// no shuffles, no SMEM P), O += P V via single-pass fp16 MMA (V fp16 k-pair
// packed). cp.async double-buffered K/V ring. 128 queries/CTA, 4 warps.
// ---------------------------------------------------------------------------
#define LDP 68                  // Q staging stride (floats) in ring area
#define LDKW 36                 // K stage row stride (words)
#define LDV16 72                // V stage row stride (words; 64 data + 8 pad)
#define ATT_STG (128 * LDKW + 32 * LDV16)    // 6912 words per stage
#define ATT_SMEM (2 * ATT_STG * 4)           // 55296 B

__global__ __launch_bounds__(128, 2) void attn_tc(
    const float* __restrict__ qg, const unsigned* __restrict__ khw,
    const unsigned* __restrict__ klw, const unsigned* __restrict__ v16w,
    unsigned* __restrict__ ohw, unsigned* __restrict__ olw)
{
    extern __shared__ __align__(16) unsigned smem_u[];
    const unsigned sb = (unsigned)__cvta_generic_to_shared(smem_u);
    float* sPf = reinterpret_cast<float*>(smem_u);   // Q staging (ring area)

    const int tid  = threadIdx.x;
    const int warp = tid >> 5;
    const int lane = tid & 31;
    const int g    = lane >> 2;
    const int c    = lane & 3;

    const int h  = blockIdx.y;
    const int b  = blockIdx.z;
    const int q0 = blockIdx.x * 128;
    const int bh8 = b * NH + h;

    auto issue = [&](int kt, int stage) {
        unsigned base = sb + stage * ATT_STG * 4;
        size_t tb  = (size_t)bh8 * SEQ + kt * 64;    // K row base (head-major)
        size_t tbp = (size_t)bh8 * 1024 + kt * 32;   // V kp-row base
#pragma unroll
        for (int it = 0; it < 12; it++) {
            int cid = it * 128 + tid;
            if (cid < 512) {
                int row = cid >> 3, ch = cid & 7;
                cp16(base + (row * LDKW + ch * 4) * 4, khw + (tb + row) * 32 + ch * 4);
            } else if (cid < 1024) {
                int c2 = cid - 512; int row = c2 >> 3, ch = c2 & 7;
                cp16(base + (64 * LDKW + row * LDKW + ch * 4) * 4,
                     klw + (tb + row) * 32 + ch * 4);
            } else {
                int c2 = cid - 1024; int row = c2 >> 4, ch = c2 & 15;
                cp16(base + (128 * LDKW + row * LDV16 + ch * 4) * 4,
                     v16w + (tbp + row) * 64 + ch * 4);
            }
        }
    };

    // ---- stage Q tile (128x64 fp32) into ring area, build bf16 frags ----
    const float* qbase = qg + (size_t)b * SEQ * DIM + h * HD;
#pragma unroll
    for (int it = 0; it < 16; it++) {
        int idx = it * 128 + tid;
        int row = idx >> 4;
        int seg = (idx & 15) * 4;
        *reinterpret_cast<float4*>(&sPf[row * LDP + seg]) =
            *reinterpret_cast<const float4*>(qbase + (size_t)(q0 + row) * DIM + seg);
    }
    __syncthreads();

    unsigned qh[2][4][4], ql[2][4][4];
#pragma unroll
    for (int mt = 0; mt < 2; mt++) {
        int r0 = warp * 32 + mt * 16 + g;
#pragma unroll
        for (int ks = 0; ks < 4; ks++) {
            float2 e00 = *reinterpret_cast<float2*>(&sPf[r0 * LDP + ks * 16 + 2 * c]);
            float2 e10 = *reinterpret_cast<float2*>(&sPf[(r0 + 8) * LDP + ks * 16 + 2 * c]);
            float2 e01 = *reinterpret_cast<float2*>(&sPf[r0 * LDP + ks * 16 + 2 * c + 8]);
            float2 e11 = *reinterpret_cast<float2*>(&sPf[(r0 + 8) * LDP + ks * 16 + 2 * c + 8]);
            qh[mt][ks][0] = bfpack(e00.x, e00.y);
            qh[mt][ks][1] = bfpack(e10.x, e10.y);
            qh[mt][ks][2] = bfpack(e01.x, e01.y);
            qh[mt][ks][3] = bfpack(e11.x, e11.y);
            ql[mt][ks][0] = bflo(e00.x, e00.y, qh[mt][ks][0]);
            ql[mt][ks][1] = bflo(e10.x, e10.y, qh[mt][ks][1]);
            ql[mt][ks][2] = bflo(e01.x, e01.y, qh[mt][ks][2]);
            ql[mt][ks][3] = bflo(e11.x, e11.y, qh[mt][ks][3]);
        }
    }
    __syncthreads();   // staging reads done before cp.async overwrites

    issue(0, 0); cp_commit();
    issue(1, 1); cp_commit();

    float O[2][8][4];
#pragma unroll
    for (int mt = 0; mt < 2; mt++)
#pragma unroll
        for (int nt = 0; nt < 8; nt++)
#pragma unroll
            for (int i = 0; i < 4; i++) O[mt][nt][i] = 0.0f;
    float ls[2][2] = {{0.0f, 0.0f}, {0.0f, 0.0f}};
    float mr[2][2] = {{-CUDART_INF_F, -CUDART_INF_F},
                      {-CUDART_INF_F, -CUDART_INF_F}};

    for (int kt = 0; kt < SEQ / 64; kt++) {
        cp_wait1();
        __syncthreads();
        const unsigned* bKh = smem_u + (kt & 1) * ATT_STG;
        const unsigned* bKl = bKh + 64 * LDKW;
        const unsigned* bV  = bKh + 128 * LDKW;

#pragma unroll
        for (int np = 0; np < 4; np++) {
            // ---- S = Q K^T (bf16x3) for the 16-key block np ----
            float s4[2][2][4];
#pragma unroll
            for (int nn = 0; nn < 2; nn++)
#pragma unroll
                for (int mt = 0; mt < 2; mt++)
#pragma unroll
                    for (int i = 0; i < 4; i++) s4[nn][mt][i] = 0.0f;
#pragma unroll
            for (int ks = 0; ks < 4; ks++) {
                unsigned bh0[2], bh1[2], bl0[2], bl1[2];
#pragma unroll
                for (int nn = 0; nn < 2; nn++) {
                    int rB = (np * 2 + nn) * 8 + g;
                    bh0[nn] = bKh[rB * LDKW + ks * 8 + c];
                    bh1[nn] = bKh[rB * LDKW + ks * 8 + c + 4];
                    bl0[nn] = bKl[rB * LDKW + ks * 8 + c];
                    bl1[nn] = bKl[rB * LDKW + ks * 8 + c + 4];
                }
#pragma unroll
                for (int nn = 0; nn < 2; nn++)
#pragma unroll
                    for (int mt = 0; mt < 2; mt++)
                        mma_bf16(s4[nn][mt], qh[mt][ks], bh0[nn], bh1[nn]);
#pragma unroll
                for (int nn = 0; nn < 2; nn++)
#pragma unroll
                    for (int mt = 0; mt < 2; mt++)
                        mma_bf16(s4[nn][mt], qh[mt][ks], bl0[nn], bl1[nn]);
#pragma unroll
                for (int nn = 0; nn < 2; nn++)
#pragma unroll
                    for (int mt = 0; mt < 2; mt++)
                        mma_bf16(s4[nn][mt], ql[mt][ks], bh0[nn], bh1[nn]);
            }

            // ---- running-max update + P = exp(s - m) packed as fp16 A-frags ----
            unsigned pa[2][4];
#pragma unroll
            for (int mt = 0; mt < 2; mt++) {
                float mg  = fmaxf(fmaxf(s4[0][mt][0], s4[0][mt][1]),
                                  fmaxf(s4[1][mt][0], s4[1][mt][1]));
                float mg8 = fmaxf(fmaxf(s4[0][mt][2], s4[0][mt][3]),
                                  fmaxf(s4[1][mt][2], s4[1][mt][3]));
                // cross-c reduce via packed fp16 max (coarse m is fine: p <= e^0.05)
                unsigned hp = h2pack(mg, mg8);
                hp = hmax2(hp, __shfl_xor_sync(0xffffffffu, hp, 1));
                hp = hmax2(hp, __shfl_xor_sync(0xffffffffu, hp, 2));
                float m0n = fmaxf(mr[mt][0], h2lo(hp));
                float m1n = fmaxf(mr[mt][1], h2hi(hp));
                float c0 = __expf(mr[mt][0] - m0n);
                float c1 = __expf(mr[mt][1] - m1n);
                mr[mt][0] = m0n; mr[mt][1] = m1n;
                ls[mt][0] *= c0; ls[mt][1] *= c1;
#pragma unroll
                for (int nt = 0; nt < 8; nt++) {
                    O[mt][nt][0] *= c0; O[mt][nt][1] *= c0;
                    O[mt][nt][2] *= c1; O[mt][nt][3] *= c1;
                }
                float p00 = __expf(s4[0][mt][0] - m0n);
                float p01 = __expf(s4[0][mt][1] - m0n);
                float p02 = __expf(s4[0][mt][2] - m1n);
                float p03 = __expf(s4[0][mt][3] - m1n);
                float p10 = __expf(s4[1][mt][0] - m0n);
                float p11 = __expf(s4[1][mt][1] - m0n);
                float p12 = __expf(s4[1][mt][2] - m1n);
                float p13 = __expf(s4[1][mt][3] - m1n);
                ls[mt][0] += (p00 + p01) + (p10 + p11);
                ls[mt][1] += (p02 + p03) + (p12 + p13);
                pa[mt][0] = h2pack(p00, p01);   // row g,   k 2c..2c+1
                pa[mt][1] = h2pack(p02, p03);   // row g+8, k 2c..2c+1
                pa[mt][2] = h2pack(p10, p11);   // row g,   k 2c+8..2c+9
                pa[mt][3] = h2pack(p12, p13);   // row g+8, k 2c+8..2c+9
            }

            // ---- O += P V (fp16 single pass) for key block np ----
#pragma unroll
            for (int ntv = 0; ntv < 8; ntv++) {
                unsigned vb0 = bV[(np * 8 + c) * LDV16 + ntv * 8 + g];
                unsigned vb1 = bV[(np * 8 + c + 4) * LDV16 + ntv * 8 + g];
                mma_f16(O[0][ntv], pa[0], vb0, vb1);
                mma_f16(O[1][ntv], pa[1], vb0, vb1);
            }
        }

        __syncthreads();    // all warps done with this stage's K/V
        if (kt + 2 < SEQ / 64) issue(kt + 2, kt & 1);
        cp_commit();
    }

    // ---- reduce ls across the 4-lane quad (r15's MISSING step), then
    //      normalize and store as bf16 hi/lo (out-proj A operand) ----
#pragma unroll
    for (int mt = 0; mt < 2; mt++)
#pragma unroll
        for (int i = 0; i < 2; i++) {
            ls[mt][i] += __shfl_xor_sync(0xffffffffu, ls[mt][i], 1);
            ls[mt][i] += __shfl_xor_sync(0xffffffffu, ls[mt][i], 2);
        }

#pragma unroll
    for (int mt = 0; mt < 2; mt++) {
        const float inv0 = 1.0f / ls[mt][0];
        const float inv1 = 1.0f / ls[mt][1];
        int qr = q0 + warp * 32 + mt * 16 + g;
        size_t r0w = ((size_t)b * SEQ + qr) * (DIM / 2) + h * (HD / 2);
        size_t r1w = ((size_t)b * SEQ + qr + 8) * (DIM / 2) + h * (HD / 2);
#pragma unroll
        for (int nt = 0; nt < 8; nt++) {
            float o0 = O[mt][nt][0] * inv0, o1 = O[mt][nt][1] * inv0;
            float o2 = O[mt][nt][2] * inv1, o3 = O[mt][nt][3] * inv1;
            unsigned h0 = bfpack(o0, o1);
            ohw[r0w + nt * 4 + c] = h0;
            olw[r0w + nt * 4 + c] = bflo(o0, o1, h0);
            unsigned h1 = bfpack(o2, o3);
            ohw[r1w + nt * 4 + c] = h1;
            olw[r1w + nt * 4 + c] = bflo(o2, o3, h1);
        }
    }
}

// ---------------------------------------------------------------------------
extern "C" void kernel_launch(void* const* d_in, const int* in_sizes, int n_in,
                              void* d_out, int out_size)
{
    const float* x     = (const float*)d_in[0];  // [4, 2048, 512]
    const float* w_qkv = (const float*)d_in[1];  // [1536, 512]
    const float* w_out = (const float*)d_in[2];  // [512, 512]
    float* out = (float*)d_out;                  // [4, 2048, 512]

    float *qb;
    unsigned short* v16b;
    unsigned *khb, *klb, *ohb, *olb, *xhb, *xlb, *wqh, *wql, *woh, *wol;
    cudaGetSymbolAddress((void**)&qb,   g_q);
    cudaGetSymbolAddress((void**)&khb,  g_kh);
    cudaGetSymbolAddress((void**)&klb,  g_kl);
    cudaGetSymbolAddress((void**)&v16b, g_v16);
    cudaGetSymbolAddress((void**)&ohb,  g_oh);
    cudaGetSymbolAddress((void**)&olb,  g_ol);
    cudaGetSymbolAddress((void**)&xhb,  g_xh);
    cudaGetSymbolAddress((void**)&xlb,  g_xl);
    cudaGetSymbolAddress((void**)&wqh,  g_wqh);
    cudaGetSymbolAddress((void**)&wql,  g_wql);
    cudaGetSymbolAddress((void**)&woh,  g_woh);
    cudaGetSymbolAddress((void**)&wol,  g_wol);

    cudaFuncSetAttribute(gemm_bf16p, cudaFuncAttributeMaxDynamicSharedMemorySize,
                         GEMM_SMEM);
    cudaFuncSetAttribute(attn_tc, cudaFuncAttributeMaxDynamicSharedMemorySize,
                         ATT_SMEM);

    // 0) convert inputs to bf16 hi/lo
    cvt_bf<<<2048, 256>>>(x, xhb, xlb, ROWS * DIM / 2);
    cvt_bf<<<1024, 256>>>(w_qkv, wqh, wql, QKV_E * DIM / 2);
    cvt_bf<<<512, 256>>>(w_out, woh, wol, DIM * DIM / 2);

    // 1) QKV projection with split epilogue (q fp32, k bf16hl, v fp16)
    {
        dim3 grid(QKV_E / 128, ROWS / 128);
        gemm_bf16p<<<grid, 256, GEMM_SMEM>>>(xhb, xlb, wqh, wql,
                                             nullptr, ROWS, QKV_E, DIM, 1,
                                             qb, khb, klb, v16b);
    }
    // 2) fused attention -> bf16 hi/lo O
    {
        dim3 grid(SEQ / 128, NH, BATCH);
        attn_tc<<<grid, 128, ATT_SMEM>>>(qb, khb, klb,
                                         (const unsigned*)v16b, ohb, olb);
    }
    // 3) output projection -> fp32 out
    {
        dim3 grid(DIM / 128, ROWS / 128);
        gemm_bf16p<<<grid, 256, GEMM_SMEM>>>(ohb, olb, woh, wol,
                                             out, ROWS, DIM, DIM, 0,
                                             nullptr, nullptr, nullptr, nullptr);
    }
}